// round 2
// baseline (speedup 1.0000x reference)
#include <cuda_runtime.h>

#define NSLOT 4096
#define NC 10
#define D 64

__device__ float g_cc[NC * D];

// ---------------- packed f32x2 helpers ----------------
typedef unsigned long long ull;

__device__ __forceinline__ ull fma2(ull a, ull b, ull c) {
    ull d;
    asm("fma.rn.f32x2 %0, %1, %2, %3;" : "=l"(d) : "l"(a), "l"(b), "l"(c));
    return d;
}
__device__ __forceinline__ float sum2(ull a) {
    unsigned lo = (unsigned)a;
    unsigned hi = (unsigned)(a >> 32);
    return __uint_as_float(lo) + __uint_as_float(hi);
}
__device__ __forceinline__ void cp16(unsigned dst, const void* src) {
    asm volatile("cp.async.cg.shared.global [%0], [%1], 16;" :: "r"(dst), "l"(src));
}

__device__ __forceinline__ float dot4(float4 a, float4 b) {
    return a.x * b.x + a.y * b.y + a.z * b.z + a.w * b.w;
}

// ======================= Phase 1: tiny sequential state update =======================
// One block, 640 threads: thread = (n, i), n = cluster (10), i = dim (64).
__global__ void __launch_bounds__(640) phase1_kernel(
    const float* __restrict__ cc0,
    const float* __restrict__ Wk, const float* __restrict__ bk,
    const float* __restrict__ Wq, const float* __restrict__ bq,
    const float* __restrict__ Wv, const float* __restrict__ bv,
    const float* __restrict__ cc_g, const float* __restrict__ cc_b,
    const float* __restrict__ W_ih, const float* __restrict__ W_hh,
    const float* __restrict__ b_ih, const float* __restrict__ b_hh,
    const float* __restrict__ ln_g, const float* __restrict__ ln_b,
    const float* __restrict__ W1, const float* __restrict__ b1,
    const float* __restrict__ W2, const float* __restrict__ b2)
{
    __shared__ float s_cc[NC * D], s_k[NC * D], s_v[NC * D];
    __shared__ float s_x[NC * D], s_q[NC * D], s_u[NC * D];
    __shared__ float s_hid[NC * 2 * D];
    __shared__ float s_attn[NC * NC], s_rs[NC];
    __shared__ float s_red[40];

    const int tid = threadIdx.x;
    const int n = tid >> 6;      // 0..9
    const int i = tid & 63;      // 0..63
    const int w = tid >> 5;      // warp 0..19 (each warp belongs to one n)

    s_cc[tid] = cc0[tid];
    __syncthreads();

    // k = cc0 @ Wk^T + bk ; v = cc0 @ Wv^T + bv
    {
        float ka = 0.f, va = 0.f;
        const float4* wkr = (const float4*)(Wk + i * D);
        const float4* wvr = (const float4*)(Wv + i * D);
        const float4* ccr = (const float4*)(s_cc + n * D);
        #pragma unroll
        for (int j = 0; j < 16; j++) {
            float4 c = ccr[j];
            ka += dot4(c, wkr[j]);
            va += dot4(c, wvr[j]);
        }
        s_k[tid] = ka + bk[i];
        s_v[tid] = va + bv[i];
    }
    __syncthreads();

    const float temp = 0.125f;  // 64^-0.5

    for (int it = 0; it < 3; it++) {
        // ---- LN(cc; cc_g, cc_b) -> s_x ----
        float x = s_cc[tid];
        {
            float s1 = x, s2 = x * x;
            #pragma unroll
            for (int o = 16; o > 0; o >>= 1) {
                s1 += __shfl_xor_sync(0xffffffffu, s1, o);
                s2 += __shfl_xor_sync(0xffffffffu, s2, o);
            }
            if ((tid & 31) == 0) { s_red[w * 2] = s1; s_red[w * 2 + 1] = s2; }
        }
        __syncthreads();
        {
            float tot = s_red[4 * n] + s_red[4 * n + 2];
            float tsq = s_red[4 * n + 1] + s_red[4 * n + 3];
            float mean = tot * (1.f / 64.f);
            float var = tsq * (1.f / 64.f) - mean * mean;
            float inv = rsqrtf(var + 1e-5f);
            s_x[tid] = (x - mean) * inv * cc_g[i] + cc_b[i];
        }
        __syncthreads();

        // ---- q = LN @ Wq^T + bq ----
        {
            float qa = 0.f;
            const float4* wr = (const float4*)(Wq + i * D);
            const float4* xr = (const float4*)(s_x + n * D);
            #pragma unroll
            for (int j = 0; j < 16; j++) qa += dot4(xr[j], wr[j]);
            s_q[tid] = qa + bq[i];
        }
        __syncthreads();

        // ---- attn[n2][m2] = temp * <k[n2], q[m2]> ----
        if (tid < 100) {
            int n2 = tid / 10, m2 = tid % 10;
            float a = 0.f;
            const float4* kr = (const float4*)(s_k + n2 * D);
            const float4* qr = (const float4*)(s_q + m2 * D);
            #pragma unroll
            for (int j = 0; j < 16; j++) a += dot4(kr[j], qr[j]);
            s_attn[n2 * 10 + m2] = a * temp;
        }
        __syncthreads();

        // softmax over axis 0 (over n, per column m), + EPS
        if (tid < 10) {
            int m = tid;
            float mx = -1e30f;
            #pragma unroll
            for (int r = 0; r < 10; r++) mx = fmaxf(mx, s_attn[r * 10 + m]);
            float e[10], sm = 0.f;
            #pragma unroll
            for (int r = 0; r < 10; r++) { e[r] = expf(s_attn[r * 10 + m] - mx); sm += e[r]; }
            float isum = 1.f / sm;
            #pragma unroll
            for (int r = 0; r < 10; r++) s_attn[r * 10 + m] = e[r] * isum + 1e-8f;
        }
        __syncthreads();
        // row sums (over m, per row n)
        if (tid < 10) {
            float rs = 0.f;
            #pragma unroll
            for (int m = 0; m < 10; m++) rs += s_attn[tid * 10 + m];
            s_rs[tid] = rs;
        }
        __syncthreads();

        // updates[n][i] = (sum_m attn[n][m] * v[m][i]) / rowsum[n]
        {
            float u = 0.f;
            #pragma unroll
            for (int m = 0; m < 10; m++) u += s_attn[n * 10 + m] * s_v[m * D + i];
            s_u[tid] = u / s_rs[n];
        }
        __syncthreads();

        // ---- GRU cell ----
        float gi[3], gh[3];
        #pragma unroll
        for (int g = 0; g < 3; g++) {
            float a = 0.f, b = 0.f;
            const float4* wi = (const float4*)(W_ih + (g * D + i) * D);
            const float4* wh = (const float4*)(W_hh + (g * D + i) * D);
            const float4* ur = (const float4*)(s_u + n * D);
            const float4* cr = (const float4*)(s_cc + n * D);
            #pragma unroll
            for (int j = 0; j < 16; j++) {
                a += dot4(ur[j], wi[j]);
                b += dot4(cr[j], wh[j]);
            }
            gi[g] = a + b_ih[g * D + i];
            gh[g] = b + b_hh[g * D + i];
        }
        float r  = 1.f / (1.f + expf(-(gi[0] + gh[0])));
        float z  = 1.f / (1.f + expf(-(gi[1] + gh[1])));
        float nn = tanhf(gi[2] + r * gh[2]);
        float ccp = x;                       // cc_prev (this thread's own element)
        float ccg = (1.f - z) * nn + z * ccp;  // GRU output

        // ---- LN(ccg; ln_g, ln_b) -> s_x  (shuffle-only reduction; s_red reuse needs sync) ----
        __syncthreads();   // all GRU reads of s_cc / s_red done
        {
            float s1 = ccg, s2 = ccg * ccg;
            #pragma unroll
            for (int o = 16; o > 0; o >>= 1) {
                s1 += __shfl_xor_sync(0xffffffffu, s1, o);
                s2 += __shfl_xor_sync(0xffffffffu, s2, o);
            }
            if ((tid & 31) == 0) { s_red[w * 2] = s1; s_red[w * 2 + 1] = s2; }
        }
        __syncthreads();
        {
            float tot = s_red[4 * n] + s_red[4 * n + 2];
            float tsq = s_red[4 * n + 1] + s_red[4 * n + 3];
            float mean = tot * (1.f / 64.f);
            float var = tsq * (1.f / 64.f) - mean * mean;
            float inv = rsqrtf(var + 1e-5f);
            s_x[tid] = (ccg - mean) * inv * ln_g[i] + ln_b[i];
        }
        __syncthreads();

        // ---- MLP hidden: [10][128], 2 elements per thread ----
        {
            const float4* xr = (const float4*)(s_x + n * D);
            float h0 = 0.f, h1 = 0.f;
            const float4* w1a = (const float4*)(W1 + i * D);
            const float4* w1b = (const float4*)(W1 + (i + 64) * D);
            #pragma unroll
            for (int j = 0; j < 16; j++) {
                float4 c = xr[j];
                h0 += dot4(c, w1a[j]);
                h1 += dot4(c, w1b[j]);
            }
            s_hid[n * 128 + i]      = fmaxf(0.f, h0 + b1[i]);
            s_hid[n * 128 + i + 64] = fmaxf(0.f, h1 + b1[i + 64]);
        }
        __syncthreads();
        // ---- cc = ccg + hidden @ W2^T + b2 ----
        {
            float o = 0.f;
            const float4* hr = (const float4*)(s_hid + n * 128);
            const float4* wr = (const float4*)(W2 + i * 128);
            #pragma unroll
            for (int j = 0; j < 32; j++) o += dot4(hr[j], wr[j]);
            ccg = ccg + o + b2[i];
        }
        __syncthreads();
        s_cc[tid] = ccg;
        __syncthreads();
    }

    g_cc[tid] = s_cc[tid];
}

// ======================= Phase 2: per-slot MLP + max (HBM-bound) =======================
// One warp per slot; each lane owns rows (lane, lane+32).
// Weights staged via cp.async into XOR-swizzled SMEM; inner loop uses packed fma.rn.f32x2.
#define SPB 4  // slots (warps) per block

extern __shared__ float p2_smem[];

__global__ void __launch_bounds__(128, 2) phase2_kernel(
    const float* __restrict__ Wa, const float* __restrict__ ba,
    const float* __restrict__ Wb, const float* __restrict__ bb,
    float* __restrict__ out)
{
    const int lane = threadIdx.x & 31;
    const int wrp  = threadIdx.x >> 5;
    const int slot = blockIdx.x * SPB + wrp;

    float* sW  = p2_smem + wrp * 4096;               // 16 KB per warp, swizzled
    float* sH  = p2_smem + SPB * 4096 + wrp * (NC * D);
    float* sCC = p2_smem + SPB * 4096 + SPB * (NC * D);

    // block-shared cc (640 floats)
    for (int t = threadIdx.x; t < NC * D; t += 128) sCC[t] = g_cc[t];
    __syncthreads();

    const unsigned sW_u = (unsigned)__cvta_generic_to_shared(sW);

    // ---- stage Wa ----
    {
        const float* gwa = Wa + (size_t)slot * 4096;
        #pragma unroll
        for (int c = 0; c < 32; c++) {
            int f = c * 32 + lane;
            int row = f >> 4, col = f & 15;
            int dst = row * 16 + (col ^ (row & 15));
            cp16(sW_u + dst * 16, gwa + f * 4);
        }
        asm volatile("cp.async.commit_group;");
    }
    const float bA0 = ba[slot * 64 + lane];
    const float bA1 = ba[slot * 64 + lane + 32];
    const float bB0 = bb[slot * 64 + lane];
    const float bB1 = bb[slot * 64 + lane + 32];
    asm volatile("cp.async.wait_group 0;");
    __syncwarp();

    const int sw0 = lane & 15;

    // ---- GEMM1: h[n][r] = relu(sum_j Wa[r][j]*cc[n][j] + ba[r]) ----
    ull acc0[NC], acc1[NC];
    #pragma unroll
    for (int n = 0; n < NC; n++) { acc0[n] = 0ull; acc1[n] = 0ull; }

    #pragma unroll 4
    for (int j4 = 0; j4 < 16; j4++) {
        int jj = j4 ^ sw0;
        const ulonglong2 w0 = *(const ulonglong2*)(sW + (lane * 16 + jj) * 4);
        const ulonglong2 w1 = *(const ulonglong2*)(sW + ((lane + 32) * 16 + jj) * 4);
        #pragma unroll
        for (int n = 0; n < NC; n++) {
            const ulonglong2 c = *(const ulonglong2*)(sCC + n * D + j4 * 4);
            acc0[n] = fma2(w0.x, c.x, acc0[n]);
            acc0[n] = fma2(w0.y, c.y, acc0[n]);
            acc1[n] = fma2(w1.x, c.x, acc1[n]);
            acc1[n] = fma2(w1.y, c.y, acc1[n]);
        }
    }
    #pragma unroll
    for (int n = 0; n < NC; n++) {
        sH[n * D + lane]      = fmaxf(0.f, sum2(acc0[n]) + bA0);
        sH[n * D + lane + 32] = fmaxf(0.f, sum2(acc1[n]) + bA1);
    }
    __syncwarp();   // all lanes done reading sW + writing sH

    // ---- stage Wb into same buffer ----
    {
        const float* gwb = Wb + (size_t)slot * 4096;
        #pragma unroll
        for (int c = 0; c < 32; c++) {
            int f = c * 32 + lane;
            int row = f >> 4, col = f & 15;
            int dst = row * 16 + (col ^ (row & 15));
            cp16(sW_u + dst * 16, gwb + f * 4);
        }
        asm volatile("cp.async.commit_group;");
        asm volatile("cp.async.wait_group 0;");
    }
    __syncwarp();

    // ---- GEMM2: out[n][r] = sum_j Wb[r][j]*h[n][j]; then max over n, + bb ----
    #pragma unroll
    for (int n = 0; n < NC; n++) { acc0[n] = 0ull; acc1[n] = 0ull; }

    #pragma unroll 4
    for (int j4 = 0; j4 < 16; j4++) {
        int jj = j4 ^ sw0;
        const ulonglong2 w0 = *(const ulonglong2*)(sW + (lane * 16 + jj) * 4);
        const ulonglong2 w1 = *(const ulonglong2*)(sW + ((lane + 32) * 16 + jj) * 4);
        #pragma unroll
        for (int n = 0; n < NC; n++) {
            const ulonglong2 c = *(const ulonglong2*)(sH + n * D + j4 * 4);
            acc0[n] = fma2(w0.x, c.x, acc0[n]);
            acc0[n] = fma2(w0.y, c.y, acc0[n]);
            acc1[n] = fma2(w1.x, c.x, acc1[n]);
            acc1[n] = fma2(w1.y, c.y, acc1[n]);
        }
    }
    float m0 = -3.4e38f, m1 = -3.4e38f;
    #pragma unroll
    for (int n = 0; n < NC; n++) {
        m0 = fmaxf(m0, sum2(acc0[n]));
        m1 = fmaxf(m1, sum2(acc1[n]));
    }
    out[slot * 64 + lane]      = m0 + bB0;
    out[slot * 64 + lane + 32] = m1 + bB1;
}

// ======================= launch =======================
extern "C" void kernel_launch(void* const* d_in, const int* in_sizes, int n_in,
                              void* d_out, int out_size)
{
    const float* cluster_centers = (const float*)d_in[0];
    const float* Wk   = (const float*)d_in[1];
    const float* bk   = (const float*)d_in[2];
    const float* Wq   = (const float*)d_in[3];
    const float* bq   = (const float*)d_in[4];
    const float* Wv   = (const float*)d_in[5];
    const float* bv   = (const float*)d_in[6];
    const float* cc_g = (const float*)d_in[7];
    const float* cc_b = (const float*)d_in[8];
    const float* W_ih = (const float*)d_in[9];
    const float* W_hh = (const float*)d_in[10];
    const float* b_ih = (const float*)d_in[11];
    const float* b_hh = (const float*)d_in[12];
    const float* ln_g = (const float*)d_in[13];
    const float* ln_b = (const float*)d_in[14];
    const float* W1   = (const float*)d_in[15];
    const float* b1   = (const float*)d_in[16];
    const float* W2   = (const float*)d_in[17];
    const float* b2   = (const float*)d_in[18];
    const float* Wa   = (const float*)d_in[19];
    const float* ba   = (const float*)d_in[20];
    const float* Wb   = (const float*)d_in[21];
    const float* bb   = (const float*)d_in[22];
    float* out = (float*)d_out;

    const int smem2 = (SPB * 4096 + SPB * NC * D + NC * D) * 4;  // 78336 B
    cudaFuncSetAttribute(phase2_kernel, cudaFuncAttributeMaxDynamicSharedMemorySize, smem2);

    phase1_kernel<<<1, 640>>>(cluster_centers, Wk, bk, Wq, bq, Wv, bv, cc_g, cc_b,
                              W_ih, W_hh, b_ih, b_hh, ln_g, ln_b, W1, b1, W2, b2);
    phase2_kernel<<<NSLOT / SPB, 128, smem2>>>(Wa, ba, Wb, bb, out);
}

// round 6
// speedup vs baseline: 2.9023x; 2.9023x over previous
#include <cuda_runtime.h>

#define NSLOT 4096
#define NC 10
#define D 64
#define PAD 68     // 64 + 4 pad: conflict-free lane-consecutive rows
#define PAD2 132   // 128 + 4 pad

__device__ float g_cc[NC * D];

// ---------------- helpers ----------------
typedef unsigned long long ull;

__device__ __forceinline__ ull fma2(ull a, ull b, ull c) {
    ull d;
    asm("fma.rn.f32x2 %0, %1, %2, %3;" : "=l"(d) : "l"(a), "l"(b), "l"(c));
    return d;
}
__device__ __forceinline__ float sum2(ull a) {
    unsigned lo = (unsigned)a;
    unsigned hi = (unsigned)(a >> 32);
    return __uint_as_float(lo) + __uint_as_float(hi);
}
__device__ __forceinline__ void cp16(unsigned dst, const void* src) {
    asm volatile("cp.async.cg.shared.global [%0], [%1], 16;" :: "r"(dst), "l"(src));
}
__device__ __forceinline__ float dot4(float4 a, float4 b) {
    return a.x * b.x + a.y * b.y + a.z * b.z + a.w * b.w;
}

// ---------------- phase1 smem layout (float offsets) ----------------
#define OFF_WQ   0
#define OFF_WIH  (OFF_WQ  + 64  * PAD)    // 4352
#define OFF_WHH  (OFF_WIH + 192 * PAD)    // 17408
#define OFF_W1   (OFF_WHH + 192 * PAD)    // 30464
#define OFF_W2   (OFF_W1  + 128 * PAD)    // 39168
#define OFF_B    (OFF_W2  + 64  * PAD2)   // 47616
// bias region: bih@0(192) bhh@192(192) b1@384(128) bq@512(64) b2@576(64)
//              ccg@640(64) ccb@704(64) lng@768(64) lnb@832(64) -> 896 total
#define OFF_WORK (OFF_B + 896)            // 48512
#define SMEM1_FLOATS (OFF_WORK + 9112)    // 57624 floats = 230496 B

// ======================= Phase 1 (R2 rewrite: smem-cached weights) =======================
__global__ void __launch_bounds__(640) phase1_kernel(
    const float* __restrict__ cc0,
    const float* __restrict__ Wk, const float* __restrict__ bk,
    const float* __restrict__ Wq, const float* __restrict__ bq,
    const float* __restrict__ Wv, const float* __restrict__ bv,
    const float* __restrict__ cc_g, const float* __restrict__ cc_b,
    const float* __restrict__ W_ih, const float* __restrict__ W_hh,
    const float* __restrict__ b_ih, const float* __restrict__ b_hh,
    const float* __restrict__ ln_g, const float* __restrict__ ln_b,
    const float* __restrict__ W1, const float* __restrict__ b1,
    const float* __restrict__ W2, const float* __restrict__ b2)
{
    extern __shared__ float sm[];
    float* sWq  = sm + OFF_WQ;
    float* sWih = sm + OFF_WIH;
    float* sWhh = sm + OFF_WHH;
    float* sW1  = sm + OFF_W1;
    float* sW2  = sm + OFF_W2;
    float* sB   = sm + OFF_B;
    float* s_cc = sm + OFF_WORK;        // 640
    float* s_k  = s_cc + 640;           // 640
    float* s_v  = s_k  + 640;           // 640
    float* s_x  = s_v  + 640;           // 640
    float* s_q  = s_x  + 640;           // 640
    float* s_u  = s_q  + 640;           // 640
    float* s_gi = s_u  + 640;           // 1920
    float* s_gh = s_gi + 1920;          // 1920
    float* s_hid= s_gh + 1920;          // 1280
    float* s_attn = s_hid + 1280;       // 100
    float* s_rs = s_attn + 100;         // 12
    float* s_red= s_rs + 12;            // 40

    const int tid = threadIdx.x;
    const int n = tid >> 6;      // 0..9
    const int i = tid & 63;      // 0..63
    const int w = tid >> 5;      // warp 0..19
    const unsigned smb = (unsigned)__cvta_generic_to_shared(sm);

    // ---- preload weights + biases into smem (cp.async, padded rows) ----
    for (int c = tid; c < 64 * 16; c += 640) {
        int r = c >> 4, o = c & 15;
        cp16(smb + (OFF_WQ + r * PAD + o * 4) * 4, Wq + r * 64 + o * 4);
    }
    for (int c = tid; c < 192 * 16; c += 640) {
        int r = c >> 4, o = c & 15;
        cp16(smb + (OFF_WIH + r * PAD + o * 4) * 4, W_ih + r * 64 + o * 4);
    }
    for (int c = tid; c < 192 * 16; c += 640) {
        int r = c >> 4, o = c & 15;
        cp16(smb + (OFF_WHH + r * PAD + o * 4) * 4, W_hh + r * 64 + o * 4);
    }
    for (int c = tid; c < 128 * 16; c += 640) {
        int r = c >> 4, o = c & 15;
        cp16(smb + (OFF_W1 + r * PAD + o * 4) * 4, W1 + r * 64 + o * 4);
    }
    for (int c = tid; c < 64 * 32; c += 640) {
        int r = c >> 5, o = c & 31;
        cp16(smb + (OFF_W2 + r * PAD2 + o * 4) * 4, W2 + r * 128 + o * 4);
    }
    if (tid < 48)  cp16(smb + (OFF_B +   0 + tid * 4) * 4, b_ih + tid * 4);
    else if (tid < 96)  cp16(smb + (OFF_B + 192 + (tid - 48) * 4) * 4, b_hh + (tid - 48) * 4);
    else if (tid < 128) cp16(smb + (OFF_B + 384 + (tid - 96) * 4) * 4, b1 + (tid - 96) * 4);
    else if (tid < 144) cp16(smb + (OFF_B + 512 + (tid - 128) * 4) * 4, bq + (tid - 128) * 4);
    else if (tid < 160) cp16(smb + (OFF_B + 576 + (tid - 144) * 4) * 4, b2 + (tid - 144) * 4);
    else if (tid < 176) cp16(smb + (OFF_B + 640 + (tid - 160) * 4) * 4, cc_g + (tid - 160) * 4);
    else if (tid < 192) cp16(smb + (OFF_B + 704 + (tid - 176) * 4) * 4, cc_b + (tid - 176) * 4);
    else if (tid < 208) cp16(smb + (OFF_B + 768 + (tid - 192) * 4) * 4, ln_g + (tid - 192) * 4);
    else if (tid < 224) cp16(smb + (OFF_B + 832 + (tid - 208) * 4) * 4, ln_b + (tid - 208) * 4);
    asm volatile("cp.async.commit_group;");

    s_cc[tid] = cc0[tid];
    __syncthreads();

    // ---- k/v from GMEM (overlaps the cp.async preload) ----
    {
        float ka = 0.f, va = 0.f;
        const float4* wkr = (const float4*)(Wk + i * D);
        const float4* wvr = (const float4*)(Wv + i * D);
        const float4* ccr = (const float4*)(s_cc + n * D);
        #pragma unroll
        for (int j = 0; j < 16; j++) {
            float4 c = ccr[j];
            ka += dot4(c, wkr[j]);
            va += dot4(c, wvr[j]);
        }
        s_k[tid] = ka + bk[i];
        s_v[tid] = va + bv[i];
    }
    asm volatile("cp.async.wait_group 0;");
    __syncthreads();

    const float temp = 0.125f;

    for (int it = 0; it < 3; it++) {
        // ---- LN1(cc) -> s_x ----
        float x = s_cc[tid];
        {
            float s1 = x, s2 = x * x;
            #pragma unroll
            for (int o = 16; o > 0; o >>= 1) {
                s1 += __shfl_xor_sync(0xffffffffu, s1, o);
                s2 += __shfl_xor_sync(0xffffffffu, s2, o);
            }
            if ((tid & 31) == 0) { s_red[w * 2] = s1; s_red[w * 2 + 1] = s2; }
        }
        __syncthreads();
        {
            float tot = s_red[4 * n] + s_red[4 * n + 2];
            float tsq = s_red[4 * n + 1] + s_red[4 * n + 3];
            float mean = tot * (1.f / 64.f);
            float var = tsq * (1.f / 64.f) - mean * mean;
            float inv = rsqrtf(var + 1e-5f);
            s_x[tid] = (x - mean) * inv * sB[640 + i] + sB[704 + i];
        }
        __syncthreads();

        // ---- q = LN @ Wq^T + bq ----
        {
            float qa = 0.f;
            const float4* wr = (const float4*)(sWq + i * PAD);
            const float4* xr = (const float4*)(s_x + n * D);
            #pragma unroll
            for (int j = 0; j < 16; j++) qa += dot4(xr[j], wr[j]);
            s_q[tid] = qa + sB[512 + i];
        }
        __syncthreads();

        // ---- attn ----
        if (tid < 100) {
            int n2 = tid / 10, m2 = tid % 10;
            float a = 0.f;
            const float4* kr = (const float4*)(s_k + n2 * D);
            const float4* qr = (const float4*)(s_q + m2 * D);
            #pragma unroll
            for (int j = 0; j < 16; j++) a += dot4(kr[j], qr[j]);
            s_attn[n2 * 10 + m2] = a * temp;
        }
        __syncthreads();
        if (tid < 10) {   // softmax over axis 0 (per column m) + EPS
            int m = tid;
            float mx = -1e30f;
            #pragma unroll
            for (int r = 0; r < 10; r++) mx = fmaxf(mx, s_attn[r * 10 + m]);
            float e[10], smv = 0.f;
            #pragma unroll
            for (int r = 0; r < 10; r++) { e[r] = expf(s_attn[r * 10 + m] - mx); smv += e[r]; }
            float isum = 1.f / smv;
            #pragma unroll
            for (int r = 0; r < 10; r++) s_attn[r * 10 + m] = e[r] * isum + 1e-8f;
        }
        __syncthreads();
        if (tid < 10) {   // row sums
            float rs = 0.f;
            #pragma unroll
            for (int m = 0; m < 10; m++) rs += s_attn[tid * 10 + m];
            s_rs[tid] = rs;
        }
        __syncthreads();

        // ---- updates ----
        {
            float u = 0.f;
            #pragma unroll
            for (int m = 0; m < 10; m++) u += s_attn[n * 10 + m] * s_v[m * D + i];
            s_u[tid] = u / s_rs[n];
        }
        __syncthreads();

        // ---- GRU gates: row-per-thread GEMM (384 threads) ----
        if (tid < 384) {
            const int which = (tid >= 192);
            const int r = tid - 192 * which;
            const float4* wrow = (const float4*)((which ? sWhh : sWih) + r * PAD);
            const float* xb = which ? s_cc : s_u;
            const float bias = sB[(which ? 192 : 0) + r];
            float acc[10];
            #pragma unroll
            for (int m = 0; m < 10; m++) acc[m] = bias;
            #pragma unroll
            for (int j = 0; j < 16; j++) {
                const float4 wv = wrow[j];
                #pragma unroll
                for (int m = 0; m < 10; m++) {
                    const float4 xv = *(const float4*)(xb + m * D + j * 4);
                    acc[m] += dot4(xv, wv);
                }
            }
            float* dst = which ? s_gh : s_gi;
            #pragma unroll
            for (int m = 0; m < 10; m++) dst[m * 192 + r] = acc[m];
        }
        __syncthreads();

        // ---- GRU pointwise + LN2 ----
        float ccg;
        {
            float ir  = s_gi[n * 192 + i];
            float iz  = s_gi[n * 192 + 64 + i];
            float inn = s_gi[n * 192 + 128 + i];
            float hr  = s_gh[n * 192 + i];
            float hz  = s_gh[n * 192 + 64 + i];
            float hn  = s_gh[n * 192 + 128 + i];
            float r  = 1.f / (1.f + expf(-(ir + hr)));
            float z  = 1.f / (1.f + expf(-(iz + hz)));
            float nn = tanhf(inn + r * hn);
            ccg = (1.f - z) * nn + z * x;
            s_cc[tid] = ccg;
            float s1 = ccg, s2 = ccg * ccg;
            #pragma unroll
            for (int o = 16; o > 0; o >>= 1) {
                s1 += __shfl_xor_sync(0xffffffffu, s1, o);
                s2 += __shfl_xor_sync(0xffffffffu, s2, o);
            }
            if ((tid & 31) == 0) { s_red[w * 2] = s1; s_red[w * 2 + 1] = s2; }
        }
        __syncthreads();
        {
            float tot = s_red[4 * n] + s_red[4 * n + 2];
            float tsq = s_red[4 * n + 1] + s_red[4 * n + 3];
            float mean = tot * (1.f / 64.f);
            float var = tsq * (1.f / 64.f) - mean * mean;
            float inv = rsqrtf(var + 1e-5f);
            s_x[tid] = (ccg - mean) * inv * sB[768 + i] + sB[832 + i];
        }
        __syncthreads();

        // ---- MLP W1: row-per-thread, 5-cluster split (256 threads) ----
        if (tid < 256) {
            const int r = tid & 127, nh = tid >> 7;
            const float4* wrow = (const float4*)(sW1 + r * PAD);
            const float b = sB[384 + r];
            float acc[5] = {b, b, b, b, b};
            #pragma unroll
            for (int j = 0; j < 16; j++) {
                const float4 wv = wrow[j];
                #pragma unroll
                for (int g = 0; g < 5; g++) {
                    const float4 xv = *(const float4*)(s_x + (nh * 5 + g) * D + j * 4);
                    acc[g] += dot4(xv, wv);
                }
            }
            #pragma unroll
            for (int g = 0; g < 5; g++)
                s_hid[(nh * 5 + g) * 128 + r] = fmaxf(0.f, acc[g]);
        }
        __syncthreads();

        // ---- MLP W2 + residual (128 threads) ----
        if (tid < 128) {
            const int r = tid & 63, nh = tid >> 6;
            const float4* wrow = (const float4*)(sW2 + r * PAD2);
            const float b = sB[576 + r];
            float acc[5] = {b, b, b, b, b};
            #pragma unroll
            for (int j = 0; j < 32; j++) {
                const float4 wv = wrow[j];
                #pragma unroll
                for (int g = 0; g < 5; g++) {
                    const float4 xv = *(const float4*)(s_hid + (nh * 5 + g) * 128 + j * 4);
                    acc[g] += dot4(xv, wv);
                }
            }
            #pragma unroll
            for (int g = 0; g < 5; g++) {
                const int m = nh * 5 + g;
                s_cc[m * D + r] += acc[g];
            }
        }
        __syncthreads();
    }

    g_cc[tid] = s_cc[tid];
}

// ======================= Phase 2: EXACT R2 version (measured 31.7us, passing) =======================
#define SPB 4

extern __shared__ float p2_smem[];

__global__ void __launch_bounds__(128, 2) phase2_kernel(
    const float* __restrict__ Wa, const float* __restrict__ ba,
    const float* __restrict__ Wb, const float* __restrict__ bb,
    float* __restrict__ out)
{
    const int lane = threadIdx.x & 31;
    const int wrp  = threadIdx.x >> 5;
    const int slot = blockIdx.x * SPB + wrp;

    float* sW  = p2_smem + wrp * 4096;
    float* sH  = p2_smem + SPB * 4096 + wrp * (NC * D);
    float* sCC = p2_smem + SPB * 4096 + SPB * (NC * D);

    for (int t = threadIdx.x; t < NC * D; t += 128) sCC[t] = g_cc[t];
    __syncthreads();

    const unsigned sW_u = (unsigned)__cvta_generic_to_shared(sW);

    {
        const float* gwa = Wa + (size_t)slot * 4096;
        #pragma unroll
        for (int c = 0; c < 32; c++) {
            int f = c * 32 + lane;
            int row = f >> 4, col = f & 15;
            int dst = row * 16 + (col ^ (row & 15));
            cp16(sW_u + dst * 16, gwa + f * 4);
        }
        asm volatile("cp.async.commit_group;");
    }
    const float bA0 = ba[slot * 64 + lane];
    const float bA1 = ba[slot * 64 + lane + 32];
    const float bB0 = bb[slot * 64 + lane];
    const float bB1 = bb[slot * 64 + lane + 32];
    asm volatile("cp.async.wait_group 0;");
    __syncwarp();

    const int sw0 = lane & 15;

    ull acc0[NC], acc1[NC];
    #pragma unroll
    for (int n = 0; n < NC; n++) { acc0[n] = 0ull; acc1[n] = 0ull; }

    #pragma unroll 4
    for (int j4 = 0; j4 < 16; j4++) {
        int jj = j4 ^ sw0;
        const ulonglong2 w0 = *(const ulonglong2*)(sW + (lane * 16 + jj) * 4);
        const ulonglong2 w1 = *(const ulonglong2*)(sW + ((lane + 32) * 16 + jj) * 4);
        #pragma unroll
        for (int n = 0; n < NC; n++) {
            const ulonglong2 c = *(const ulonglong2*)(sCC + n * D + j4 * 4);
            acc0[n] = fma2(w0.x, c.x, acc0[n]);
            acc0[n] = fma2(w0.y, c.y, acc0[n]);
            acc1[n] = fma2(w1.x, c.x, acc1[n]);
            acc1[n] = fma2(w1.y, c.y, acc1[n]);
        }
    }
    #pragma unroll
    for (int n = 0; n < NC; n++) {
        sH[n * D + lane]      = fmaxf(0.f, sum2(acc0[n]) + bA0);
        sH[n * D + lane + 32] = fmaxf(0.f, sum2(acc1[n]) + bA1);
    }
    __syncwarp();

    {
        const float* gwb = Wb + (size_t)slot * 4096;
        #pragma unroll
        for (int c = 0; c < 32; c++) {
            int f = c * 32 + lane;
            int row = f >> 4, col = f & 15;
            int dst = row * 16 + (col ^ (row & 15));
            cp16(sW_u + dst * 16, gwb + f * 4);
        }
        asm volatile("cp.async.commit_group;");
        asm volatile("cp.async.wait_group 0;");
    }
    __syncwarp();

    #pragma unroll
    for (int n = 0; n < NC; n++) { acc0[n] = 0ull; acc1[n] = 0ull; }

    #pragma unroll 4
    for (int j4 = 0; j4 < 16; j4++) {
        int jj = j4 ^ sw0;
        const ulonglong2 w0 = *(const ulonglong2*)(sW + (lane * 16 + jj) * 4);
        const ulonglong2 w1 = *(const ulonglong2*)(sW + ((lane + 32) * 16 + jj) * 4);
        #pragma unroll
        for (int n = 0; n < NC; n++) {
            const ulonglong2 c = *(const ulonglong2*)(sH + n * D + j4 * 4);
            acc0[n] = fma2(w0.x, c.x, acc0[n]);
            acc0[n] = fma2(w0.y, c.y, acc0[n]);
            acc1[n] = fma2(w1.x, c.x, acc1[n]);
            acc1[n] = fma2(w1.y, c.y, acc1[n]);
        }
    }
    float m0 = -3.4e38f, m1 = -3.4e38f;
    #pragma unroll
    for (int n = 0; n < NC; n++) {
        m0 = fmaxf(m0, sum2(acc0[n]));
        m1 = fmaxf(m1, sum2(acc1[n]));
    }
    out[slot * 64 + lane]      = m0 + bB0;
    out[slot * 64 + lane + 32] = m1 + bB1;
}

// ======================= launch =======================
extern "C" void kernel_launch(void* const* d_in, const int* in_sizes, int n_in,
                              void* d_out, int out_size)
{
    const float* cluster_centers = (const float*)d_in[0];
    const float* Wk   = (const float*)d_in[1];
    const float* bk   = (const float*)d_in[2];
    const float* Wq   = (const float*)d_in[3];
    const float* bq   = (const float*)d_in[4];
    const float* Wv   = (const float*)d_in[5];
    const float* bv   = (const float*)d_in[6];
    const float* cc_g = (const float*)d_in[7];
    const float* cc_b = (const float*)d_in[8];
    const float* W_ih = (const float*)d_in[9];
    const float* W_hh = (const float*)d_in[10];
    const float* b_ih = (const float*)d_in[11];
    const float* b_hh = (const float*)d_in[12];
    const float* ln_g = (const float*)d_in[13];
    const float* ln_b = (const float*)d_in[14];
    const float* W1   = (const float*)d_in[15];
    const float* b1   = (const float*)d_in[16];
    const float* W2   = (const float*)d_in[17];
    const float* b2   = (const float*)d_in[18];
    const float* Wa   = (const float*)d_in[19];
    const float* ba   = (const float*)d_in[20];
    const float* Wb   = (const float*)d_in[21];
    const float* bb   = (const float*)d_in[22];
    float* out = (float*)d_out;

    const int smem1 = SMEM1_FLOATS * 4;   // 230496 B
    cudaFuncSetAttribute(phase1_kernel, cudaFuncAttributeMaxDynamicSharedMemorySize, smem1);

    const int smem2 = (SPB * 4096 + SPB * NC * D + NC * D) * 4;  // 78336 B
    cudaFuncSetAttribute(phase2_kernel, cudaFuncAttributeMaxDynamicSharedMemorySize, smem2);

    phase1_kernel<<<1, 640, smem1>>>(cluster_centers, Wk, bk, Wq, bq, Wv, bv, cc_g, cc_b,
                                     W_ih, W_hh, b_ih, b_hh, ln_g, ln_b, W1, b1, W2, b2);
    phase2_kernel<<<NSLOT / SPB, 128, smem2>>>(Wa, ba, Wb, bb, out);
}